// round 17
// baseline (speedup 1.0000x reference)
#include <cuda_runtime.h>
#include <cuda_bf16.h>
#include <cstdint>

#define EPS 1e-16f
#define W 1024
#define H 1024
#define ROWS 16         // output rows per block (band)
#define TPB 256         // 256 threads * 4 px = 1024 = full row width
#define BANDS (H / ROWS)

typedef unsigned long long ull;

// ---- packed f32x2 helpers (sm_103a) ----
__device__ __forceinline__ ull pk2(float lo, float hi) {
    ull r; asm("mov.b64 %0, {%1, %2};" : "=l"(r) : "f"(lo), "f"(hi)); return r;
}
#define UNPK2(v, a, b) asm("mov.b64 {%0, %1}, %2;" : "=f"(a), "=f"(b) : "l"(v))
__device__ __forceinline__ ull f2add(ull a, ull b) {
    ull r; asm("add.rn.f32x2 %0, %1, %2;" : "=l"(r) : "l"(a), "l"(b)); return r;
}
__device__ __forceinline__ ull f2mul(ull a, ull b) {
    ull r; asm("mul.rn.f32x2 %0, %1, %2;" : "=l"(r) : "l"(a), "l"(b)); return r;
}
__device__ __forceinline__ ull f2fma(ull a, ull b, ull c) {
    ull r; asm("fma.rn.f32x2 %0, %1, %2, %3;" : "=l"(r) : "l"(a), "l"(b), "l"(c)); return r;
}

// out(x,y) = (dxf+dyf)*invF - dxf(x-1,y)*invF(x-1,y) - dyf(x,y-1)*invF(x,y-1)
// Tall band, rolling 3-row register window, 3-slot smem edge ring, packed math.
__global__ __launch_bounds__(TPB, 7)
void curvature_kernel(const float* __restrict__ u, float* __restrict__ out) {
    const int tile = blockIdx.x;            // b * BANDS + band
    const int b    = tile >> 6;             // BANDS = 64
    const int x0   = (tile & 63) * ROWS;    // first output row
    const int t    = threadIdx.x;
    const int y    = t * 4;                 // first output col (float4 granule)

    const float* ub = u   + (size_t)b * (H * W);
    float*       ob = out + (size_t)b * (H * W);

    // edge ring: slot s holds edges of padded local row r where r%3==s
    // eL[s][t] read as left halo of thread t (written by t-1 at [t+1]; reflect at [0])
    // eR[s][t+1] read as right halo of thread t (reflect at [TPB])
    __shared__ float eL[3][TPB + 1];
    __shared__ float eR[3][TPB + 1];

    auto ldrow = [&](int pr) -> float4 {
        int r = (pr < 0) ? 1 : ((pr >= H) ? (H - 2) : pr);
        return *reinterpret_cast<const float4*>(ub + (size_t)r * W + y);
    };

    const ull NEG1 = pk2(-1.0f, -1.0f);
    const ull EPS2 = pk2(EPS, EPS);

    // prologue: local padded rows 0,1 resident; publish their edges; prefetch row 2
    float4 q0 = ldrow(x0 - 1);
    float4 q1 = ldrow(x0);
    eL[0][t + 1] = q0.w;  eR[0][t] = q0.x;
    eL[1][t + 1] = q1.w;  eR[1][t] = q1.x;
    if (t == 0)       { eL[0][0] = q0.y;   eL[1][0] = q1.y; }       // col -1 -> 1
    if (t == TPB - 1) { eR[0][TPB] = q0.z; eR[1][TPB] = q1.z; }     // col W -> W-2
    float4 qn = ldrow(x0 + 1);              // local row 2

    ull Ap01 = 0ull, Ap23 = 0ull;           // A = dxf*invF from previous F-row

    #pragma unroll
    for (int k = 0; k <= ROWS; ++k) {
        const int sk  = k % 3;
        const int sk1 = (k + 1) % 3;
        const int sk2 = (k + 2) % 3;

        // bar: (a) makes slots sk,sk1 visible, (b) separates prior readers of
        // slot sk2 (= slot k-1) from the overwrite below (WAR).
        __syncthreads();

        // publish edges of local row k+2 (qn) into slot sk2
        eL[sk2][t + 1] = qn.w;  eR[sk2][t] = qn.x;
        if (t == 0)       eL[sk2][0]   = qn.y;
        if (t == TPB - 1) eR[sk2][TPB] = qn.z;

        // shift window; prefetch local row k+3 (global row x0+k+2)
        const float4 a0 = q0, a1 = q1;      // rows k, k+1 for this compute
        q0 = q1; q1 = qn;
        if (k <= ROWS - 2) qn = ldrow(x0 + k + 2);

        // halos of F-row k
        const float l0v = eL[sk][t];
        const float l1v = eL[sk1][t];
        const float r0v = eR[sk][t + 1];

        // ---- scalar m-column (col y-1) F-term ----
        const float dxm = l1v - l0v, dym = a0.x - l0v;
        const float iFm = rsqrtf(fmaf(dxm, dxm, fmaf(dym, dym, EPS)));
        const float Bm  = dym * iFm;

        // ---- packed cols y .. y+3 ----
        const ull q0_01 = pk2(a0.x, a0.y);
        const ull q0_12 = pk2(a0.y, a0.z);
        const ull q0_23 = pk2(a0.z, a0.w);
        const ull q0_3r = pk2(a0.w, r0v);
        const ull q1_01 = pk2(a1.x, a1.y);
        const ull q1_23 = pk2(a1.z, a1.w);

        const ull dx01 = f2fma(q0_01, NEG1, q1_01);   // q1 - q0
        const ull dx23 = f2fma(q0_23, NEG1, q1_23);
        const ull dy01 = f2fma(q0_01, NEG1, q0_12);   // shift - q0
        const ull dy23 = f2fma(q0_23, NEG1, q0_3r);

        const ull n01 = f2fma(dx01, dx01, f2fma(dy01, dy01, EPS2));
        const ull n23 = f2fma(dx23, dx23, f2fma(dy23, dy23, EPS2));
        float n0, n1, n2, n3;
        UNPK2(n01, n0, n1);
        UNPK2(n23, n2, n3);
        const float iF0 = rsqrtf(n0), iF1 = rsqrtf(n1);
        const float iF2 = rsqrtf(n2), iF3 = rsqrtf(n3);
        const ull iF01 = pk2(iF0, iF1);
        const ull iF23 = pk2(iF2, iF3);

        if (k > 0) {
            const ull s01 = f2add(dx01, dy01);
            const ull s23 = f2add(dx23, dy23);
            const ull P01 = f2mul(dy01, iF01);        // dy*iF (B-products)
            const ull P23 = f2mul(dy23, iF23);
            float P0, P1, P2, P3;
            UNPK2(P01, P0, P1);
            UNPK2(P23, P2, P3);
            const ull Bo01 = pk2(Bm, P0);
            const ull Bo23 = pk2(P1, P2);
            // o = (S*iF - Ap) - B   (same association as scalar version)
            const ull o01 = f2fma(Bo01, NEG1, f2fma(Ap01, NEG1, f2mul(s01, iF01)));
            const ull o23 = f2fma(Bo23, NEG1, f2fma(Ap23, NEG1, f2mul(s23, iF23)));
            float4 o;
            UNPK2(o01, o.x, o.y);
            UNPK2(o23, o.z, o.w);
            *reinterpret_cast<float4*>(ob + (size_t)(x0 + k - 1) * W + y) = o;
        }
        Ap01 = f2mul(dx01, iF01);
        Ap23 = f2mul(dx23, iF23);
    }
}

extern "C" void kernel_launch(void* const* d_in, const int* in_sizes, int n_in,
                              void* d_out, int out_size) {
    const float* u = (const float*)d_in[0];
    float* out = (float*)d_out;
    const int batch = in_sizes[0] / (H * W);   // 16
    const int blocks = batch * BANDS;          // 1024
    curvature_kernel<<<blocks, TPB>>>(u, out);
}